// round 2
// baseline (speedup 1.0000x reference)
#include <cuda_runtime.h>
#include <math.h>

// Problem constants
#define BB 4
#define SS 4096
#define DD 2048
#define NH 16
#define HH 128
#define MTOT (BB * SS)   // 16384

// GEMM tiling
#define BM 128
#define BN 128
#define BK 16
#define TM 8
#define TN 8

typedef unsigned long long ull;

// ---- packed fp32x2 helpers (Blackwell FFMA2 — only reachable via PTX) ----
__device__ __forceinline__ ull ffma2(ull a, ull b, ull c) {
    ull d;
    asm("fma.rn.f32x2 %0, %1, %2, %3;" : "=l"(d) : "l"(a), "l"(b), "l"(c));
    return d;
}
__device__ __forceinline__ ull pack2(float lo, float hi) {
    ull r;
    asm("mov.b64 %0, {%1, %2};" : "=l"(r) : "f"(lo), "f"(hi));
    return r;
}
__device__ __forceinline__ void unpack2(ull v, float& lo, float& hi) {
    asm("mov.b64 {%0, %1}, %2;" : "=f"(lo), "=f"(hi) : "l"(v));
}

// ---- scratch (device globals; no allocation allowed) ----
__device__ float g_x[33554432];  // (B,S,D) post-input-projection (+bias)
__device__ float g_y[33554432];  // (B,S,D) scan outputs

// ============================================================================
// GEMM: C[MTOT, 2048] = A[MTOT, 2048] @ W[2048, 2048] (+ bias)
// A row-major (m,k), W row-major (k,n). 128x128x16 tiles, 256 threads,
// 8x8 microtile with f32x2-packed accumulators (pairs along n).
// ============================================================================
__global__ __launch_bounds__(256, 2)
void gemm_kernel(const float* __restrict__ A, const float* __restrict__ W,
                 const float* __restrict__ bias, float* __restrict__ C) {
    __shared__ __align__(16) float As[BK][BM + 4];  // transposed A tile
    __shared__ __align__(16) float Bs[BK][BN + 4];

    const int t  = threadIdx.x;
    const int tx = t & 15;       // 0..15 -> n microtile
    const int ty = t >> 4;       // 0..15 -> m microtile
    const size_t m0 = (size_t)blockIdx.y * BM;
    const size_t n0 = (size_t)blockIdx.x * BN;

    ull acc[TM][TN / 2];
    #pragma unroll
    for (int i = 0; i < TM; i++)
        #pragma unroll
        for (int j = 0; j < TN / 2; j++) acc[i][j] = 0ull;

    for (int k0 = 0; k0 < DD; k0 += BK) {
        __syncthreads();
        // Load A tile (128 x 16) -> transposed As[k][m]
        #pragma unroll
        for (int i = 0; i < 2; i++) {
            int f4  = t + i * 256;
            int row = f4 >> 2;
            int kq  = (f4 & 3) * 4;
            float4 v = *(const float4*)(A + (m0 + row) * DD + k0 + kq);
            As[kq + 0][row] = v.x;
            As[kq + 1][row] = v.y;
            As[kq + 2][row] = v.z;
            As[kq + 3][row] = v.w;
        }
        // Load B tile (16 x 128) -> Bs[k][n]
        #pragma unroll
        for (int i = 0; i < 2; i++) {
            int f4 = t + i * 256;
            int kr = f4 >> 5;
            int ev = (f4 & 31) * 4;
            float4 v = *(const float4*)(W + (size_t)(k0 + kr) * DD + n0 + ev);
            *(float4*)&Bs[kr][ev] = v;
        }
        __syncthreads();

        #pragma unroll
        for (int k = 0; k < BK; k++) {
            float4 a0 = *(const float4*)&As[k][ty * TM];
            float4 a1 = *(const float4*)&As[k][ty * TM + 4];
            ulonglong2 b01 = *(const ulonglong2*)&Bs[k][tx * TN];
            ulonglong2 b23 = *(const ulonglong2*)&Bs[k][tx * TN + 4];
            ull bv0 = b01.x, bv1 = b01.y, bv2 = b23.x, bv3 = b23.y;
            float av[8] = {a0.x, a0.y, a0.z, a0.w, a1.x, a1.y, a1.z, a1.w};
            #pragma unroll
            for (int i = 0; i < TM; i++) {
                ull ad = pack2(av[i], av[i]);
                acc[i][0] = ffma2(ad, bv0, acc[i][0]);
                acc[i][1] = ffma2(ad, bv1, acc[i][1]);
                acc[i][2] = ffma2(ad, bv2, acc[i][2]);
                acc[i][3] = ffma2(ad, bv3, acc[i][3]);
            }
        }
    }

    // Epilogue: unpack, add bias, store
    float bv[8];
    if (bias != nullptr) {
        float4 q0 = *(const float4*)(bias + n0 + tx * TN);
        float4 q1 = *(const float4*)(bias + n0 + tx * TN + 4);
        bv[0] = q0.x; bv[1] = q0.y; bv[2] = q0.z; bv[3] = q0.w;
        bv[4] = q1.x; bv[5] = q1.y; bv[6] = q1.z; bv[7] = q1.w;
    } else {
        #pragma unroll
        for (int j = 0; j < 8; j++) bv[j] = 0.0f;
    }

    #pragma unroll
    for (int i = 0; i < TM; i++) {
        float o[8];
        #pragma unroll
        for (int j = 0; j < TN / 2; j++) unpack2(acc[i][j], o[2 * j], o[2 * j + 1]);
        #pragma unroll
        for (int j = 0; j < 8; j++) o[j] += bv[j];
        float* crow = C + (m0 + ty * TM + i) * DD + n0 + tx * TN;
        *(float4*)(crow + 0) = make_float4(o[0], o[1], o[2], o[3]);
        *(float4*)(crow + 4) = make_float4(o[4], o[5], o[6], o[7]);
    }
}

// ============================================================================
// Scan: 64 blocks, one per (b, n). Per block: W_n column-per-thread in regs
// (128 regs/thread), state ping-pong in shared, f32x2-packed matvec,
// tanh, x prefetched 2 steps ahead. No inter-block sync needed.
// ============================================================================
__global__ __launch_bounds__(128, 1)
void scan_kernel(const float* __restrict__ x, const float* __restrict__ s0,
                 const float* __restrict__ SW, float* __restrict__ y) {
    const int b = blockIdx.x >> 4;
    const int n = blockIdx.x & 15;
    const int k = threadIdx.x;

    // W column k of head n, packed in (even,odd)-h pairs. out[k] = sum_h s[h]*W[h][k]
    const float* Wn = SW + (size_t)n * HH * HH;
    ull w2[64];
    #pragma unroll
    for (int j = 0; j < 64; j++)
        w2[j] = pack2(Wn[(2 * j) * HH + k], Wn[(2 * j + 1) * HH + k]);

    __shared__ __align__(16) float sbuf[2][HH];
    sbuf[0][k] = s0[((size_t)b * NH + n) * HH + k];
    __syncthreads();

    const float* xp = x + (size_t)b * SS * DD + n * HH + k;
    float*       yp = y + (size_t)b * SS * DD + n * HH + k;

    float xa = xp[0];
    float xb = xp[DD];

    for (int t = 0; t < SS; t++) {
        // issue prefetch for t+2 before the heavy FMA chain
        float xn = 0.0f;
        if (t + 2 < SS) xn = xp[(size_t)(t + 2) * DD];

        const ulonglong2* s4 = (const ulonglong2*)sbuf[t & 1];
        ull a0 = 0ull, a1 = 0ull, a2 = 0ull, a3 = 0ull;
        #pragma unroll
        for (int j = 0; j < 16; j++) {
            ulonglong2 p = s4[2 * j];
            ulonglong2 q = s4[2 * j + 1];
            a0 = ffma2(p.x, w2[4 * j + 0], a0);
            a1 = ffma2(p.y, w2[4 * j + 1], a1);
            a2 = ffma2(q.x, w2[4 * j + 2], a2);
            a3 = ffma2(q.y, w2[4 * j + 3], a3);
        }
        float l0, h0, l1, h1, l2, h2, l3, h3;
        unpack2(a0, l0, h0); unpack2(a1, l1, h1);
        unpack2(a2, l2, h2); unpack2(a3, l3, h3);
        float dot = ((l0 + h0) + (l1 + h1)) + ((l2 + h2) + (l3 + h3));

        float v = tanhf(dot + xa);
        yp[(size_t)t * DD] = v;
        sbuf[(t + 1) & 1][k] = v;

        xa = xb;
        xb = xn;
        __syncthreads();
    }
}

// ============================================================================
// Launch: input-proj GEMM -> scan -> output-proj GEMM (same stream, ordered)
// ============================================================================
extern "C" void kernel_launch(void* const* d_in, const int* in_sizes, int n_in,
                              void* d_out, int out_size) {
    const float* input  = (const float*)d_in[0];
    const float* state0 = (const float*)d_in[1];
    const float* w_in   = (const float*)d_in[2];
    const float* b_in   = (const float*)d_in[3];
    const float* sw     = (const float*)d_in[4];
    const float* w_out  = (const float*)d_in[5];
    float* out = (float*)d_out;

    float* xbuf = nullptr;
    float* ybuf = nullptr;
    cudaGetSymbolAddress((void**)&xbuf, g_x);
    cudaGetSymbolAddress((void**)&ybuf, g_y);

    dim3 grid(DD / BN, MTOT / BM);  // (16, 128)
    gemm_kernel<<<grid, 256>>>(input, w_in, b_in, xbuf);
    scan_kernel<<<BB * NH, HH>>>(xbuf, state0, sw, ybuf);
    gemm_kernel<<<grid, 256>>>(ybuf, w_out, nullptr, out);
}

// round 4
// speedup vs baseline: 2.0397x; 2.0397x over previous
#include <cuda_runtime.h>
#include <math.h>
#include <stdint.h>

// Problem constants
#define BB 4
#define SS 4096
#define DD 2048
#define NH 16
#define HH 128
#define MTOT (BB * SS)   // 16384

typedef unsigned long long ull;

// ---- packed fp32x2 helpers (Blackwell FFMA2 — only reachable via PTX) ----
__device__ __forceinline__ ull ffma2(ull a, ull b, ull c) {
    ull d;
    asm("fma.rn.f32x2 %0, %1, %2, %3;" : "=l"(d) : "l"(a), "l"(b), "l"(c));
    return d;
}
__device__ __forceinline__ ull addf2(ull a, ull b) {
    ull d;
    asm("add.rn.f32x2 %0, %1, %2;" : "=l"(d) : "l"(a), "l"(b));
    return d;
}
__device__ __forceinline__ ull pack2(float lo, float hi) {
    ull r;
    asm("mov.b64 %0, {%1, %2};" : "=l"(r) : "f"(lo), "f"(hi));
    return r;
}
__device__ __forceinline__ void unpack2(ull v, float& lo, float& hi) {
    asm("mov.b64 {%0, %1}, %2;" : "=f"(lo), "=f"(hi) : "l"(v));
}
__device__ __forceinline__ uint32_t smem_u32(const void* p) {
    uint32_t a;
    asm("{ .reg .u64 t; cvta.to.shared.u64 t, %1; cvt.u32.u64 %0, t; }" : "=r"(a) : "l"(p));
    return a;
}

// fast tanh: (e^{2x}-1)/(e^{2x}+1) via MUFU ex2/rcp; rel err ~1e-7
__device__ __forceinline__ float fast_tanh(float x) {
    float t = fminf(x * 2.885390081777927f, 80.0f);  // 2*log2(e), clamp vs overflow
    float e;
    asm("ex2.approx.f32 %0, %1;" : "=f"(e) : "f"(t));
    float r;
    asm("rcp.approx.f32 %0, %1;" : "=f"(r) : "f"(e + 1.0f));
    return (e - 1.0f) * r;
}

// ---- mma.sync / ldmatrix (plain PTX, assembles at compute_103) ----
__device__ __forceinline__ void ldsm4(uint32_t* r, uint32_t addr) {
    asm volatile("ldmatrix.sync.aligned.m8n8.x4.shared.b16 {%0,%1,%2,%3}, [%4];"
                 : "=r"(r[0]), "=r"(r[1]), "=r"(r[2]), "=r"(r[3]) : "r"(addr));
}
__device__ __forceinline__ void ldsm4t(uint32_t* r, uint32_t addr) {
    asm volatile("ldmatrix.sync.aligned.m8n8.x4.trans.shared.b16 {%0,%1,%2,%3}, [%4];"
                 : "=r"(r[0]), "=r"(r[1]), "=r"(r[2]), "=r"(r[3]) : "r"(addr));
}
__device__ __forceinline__ void mma_bf16(float* c, const uint32_t* a, uint32_t b0, uint32_t b1) {
    asm volatile("mma.sync.aligned.m16n8k16.row.col.f32.bf16.bf16.f32 "
                 "{%0,%1,%2,%3}, {%4,%5,%6,%7}, {%8,%9}, {%0,%1,%2,%3};"
                 : "+f"(c[0]), "+f"(c[1]), "+f"(c[2]), "+f"(c[3])
                 : "r"(a[0]), "r"(a[1]), "r"(a[2]), "r"(a[3]), "r"(b0), "r"(b1));
}

// ---- scratch (device globals; no allocation allowed) ----
__device__ float g_x[33554432];  // (B,S,D) post-input-projection (+bias)
__device__ float g_y[33554432];  // (B,S,D) scan outputs

// ============================================================================
// bf16 3-product-split GEMM via mma.sync:
//   C[MTOT,2048] = A[MTOT,2048] @ W[2048,2048] (+bias), fp32-grade accuracy.
// Tile 128x128, BK=32, 256 threads = 8 warps (4M x 2N), each warp 32x64.
// smem per stage: Ahi/Alo 128x32 bf16 (8KB each), Bhi/Blo 32x128 bf16 (8KB each)
// double buffered = 64KB dynamic smem. Swizzled for conflict-free ldmatrix.
// ============================================================================
#define STG 32768
#define AHI 0
#define ALO 8192
#define BHI 16384
#define BLO 24576

// A store/ldmatrix offset: row r (0..127, 64B rows), 16B chunk c (0..3)
__device__ __forceinline__ uint32_t aoff(int r, int c) {
    return (uint32_t)(r * 64 + ((c ^ ((r >> 1) & 3)) * 16));
}
// B: k-row kr (0..31, 256B rows), 16B chunk c (0..15)
__device__ __forceinline__ uint32_t boff(int kr, int c) {
    return (uint32_t)(kr * 256 + ((c ^ (kr & 7)) * 16));
}

// convert 8 fp32 -> bf16 hi chunk + bf16 lo chunk, store both to smem
__device__ __forceinline__ void cvt_store(uint32_t dhi, uint32_t dlo, float4 v0, float4 v1) {
    float f[8] = {v0.x, v0.y, v0.z, v0.w, v1.x, v1.y, v1.z, v1.w};
    uint32_t h[4], l[4];
    #pragma unroll
    for (int p = 0; p < 4; p++) {
        uint32_t hp;
        asm("cvt.rn.bf16x2.f32 %0, %1, %2;" : "=r"(hp) : "f"(f[2 * p + 1]), "f"(f[2 * p]));
        float h0 = __uint_as_float(hp << 16);
        float h1 = __uint_as_float(hp & 0xFFFF0000u);
        float l0 = f[2 * p] - h0;
        float l1 = f[2 * p + 1] - h1;
        uint32_t lp;
        asm("cvt.rn.bf16x2.f32 %0, %1, %2;" : "=r"(lp) : "f"(l1), "f"(l0));
        h[p] = hp; l[p] = lp;
    }
    asm volatile("st.shared.v4.b32 [%0], {%1,%2,%3,%4};"
                 :: "r"(dhi), "r"(h[0]), "r"(h[1]), "r"(h[2]), "r"(h[3]));
    asm volatile("st.shared.v4.b32 [%0], {%1,%2,%3,%4};"
                 :: "r"(dlo), "r"(l[0]), "r"(l[1]), "r"(l[2]), "r"(l[3]));
}

__global__ __launch_bounds__(256, 1)
void gemm_mma_kernel(const float* __restrict__ A, const float* __restrict__ W,
                     const float* __restrict__ bias, float* __restrict__ C) {
    extern __shared__ __align__(128) char smem[];
    const uint32_t sb = smem_u32(smem);

    const int t    = threadIdx.x;
    const int lane = t & 31;
    const int wid  = t >> 5;
    const int wm   = wid >> 1;   // 0..3 -> m offset wm*32
    const int wn   = wid & 1;    // 0..1 -> n offset wn*64
    const size_t m0 = (size_t)blockIdx.y * 128;
    const size_t n0 = (size_t)blockIdx.x * 128;

    // ---- gmem load pointers (octet = 8 floats = 32B) ----
    const float* gA0 = A + (m0 + (t >> 2)) * DD + (t & 3) * 8;           // rows 0..63
    const float* gA1 = gA0 + (size_t)64 * DD;                            // rows 64..127
    const float* gB0 = W + (size_t)(t >> 4) * DD + n0 + (t & 15) * 8;    // k rows 0..15
    const float* gB1 = gB0 + (size_t)16 * DD;                            // k rows 16..31

    // ---- smem store byte offsets (within stage) ----
    const uint32_t sa0 = aoff(t >> 2, t & 3);
    const uint32_t sa1 = aoff((t >> 2) + 64, t & 3);
    const uint32_t sb0 = boff(t >> 4, t & 15);
    const uint32_t sb1 = boff((t >> 4) + 16, t & 15);

    // ---- ldmatrix addresses (byte offsets within stage) ----
    // A: lanes 0-7 -> rows g (k lo), 8-15 -> rows g+8 (k lo), 16-23 -> g (k hi), 24-31 -> g+8 (k hi)
    const int arow = wm * 32 + (lane & 7) + ((lane >> 3) & 1) * 8;
    const int akh  = (lane >> 4) & 1;
    uint32_t aA[2][2];  // [mtile][kstep]
    #pragma unroll
    for (int mt = 0; mt < 2; mt++)
        #pragma unroll
        for (int ks = 0; ks < 2; ks++)
            aA[mt][ks] = aoff(arow + mt * 16, ks * 2 + akh);
    // B (trans): lanes 0-7: k lo rows / n pair0; 8-15: k hi / pair0; 16-23: k lo / pair1; 24-31: k hi / pair1
    const int bpair = lane >> 4;
    const int bkr0  = ((lane >> 3) & 1) * 8 + (lane & 7);
    uint32_t aB[2][4];  // [kstep][bquad]
    #pragma unroll
    for (int ks = 0; ks < 2; ks++)
        #pragma unroll
        for (int bq = 0; bq < 4; bq++)
            aB[ks][bq] = boff(ks * 16 + bkr0, wn * 8 + bq * 2 + bpair);

    float acc[2][8][4];
    #pragma unroll
    for (int mt = 0; mt < 2; mt++)
        #pragma unroll
        for (int nt = 0; nt < 8; nt++)
            #pragma unroll
            for (int i = 0; i < 4; i++) acc[mt][nt][i] = 0.0f;

    float4 ra0a, ra0b, ra1a, ra1b, rb0a, rb0b, rb1a, rb1b;

    // ---- prologue: load + convert tile 0 into stage 0 ----
    ra0a = *(const float4*)(gA0);     ra0b = *(const float4*)(gA0 + 4);
    ra1a = *(const float4*)(gA1);     ra1b = *(const float4*)(gA1 + 4);
    rb0a = *(const float4*)(gB0);     rb0b = *(const float4*)(gB0 + 4);
    rb1a = *(const float4*)(gB1);     rb1b = *(const float4*)(gB1 + 4);
    {
        uint32_t s = sb;
        cvt_store(s + AHI + sa0, s + ALO + sa0, ra0a, ra0b);
        cvt_store(s + AHI + sa1, s + ALO + sa1, ra1a, ra1b);
        cvt_store(s + BHI + sb0, s + BLO + sb0, rb0a, rb0b);
        cvt_store(s + BHI + sb1, s + BLO + sb1, rb1a, rb1b);
    }
    __syncthreads();

    for (int tile = 0; tile < 64; tile++) {
        const uint32_t cur = sb + (uint32_t)(tile & 1) * STG;
        const uint32_t nxt = sb + (uint32_t)((tile + 1) & 1) * STG;

        // prefetch next tile (gmem -> regs) before compute, to overlap latency
        if (tile < 63) {
            gA0 += 32; gA1 += 32;
            gB0 += (size_t)32 * DD; gB1 += (size_t)32 * DD;
            ra0a = *(const float4*)(gA0);     ra0b = *(const float4*)(gA0 + 4);
            ra1a = *(const float4*)(gA1);     ra1b = *(const float4*)(gA1 + 4);
            rb0a = *(const float4*)(gB0);     rb0b = *(const float4*)(gB0 + 4);
            rb1a = *(const float4*)(gB1);     rb1b = *(const float4*)(gB1 + 4);
        }

        // compute on current stage: 2 k-steps x (3 passes x 2 mtiles x 8 ntiles)
        #pragma unroll
        for (int ks = 0; ks < 2; ks++) {
            uint32_t ah[2][4], al[2][4], bh[4][4], bl[4][4];
            ldsm4(ah[0], cur + AHI + aA[0][ks]);
            ldsm4(ah[1], cur + AHI + aA[1][ks]);
            ldsm4(al[0], cur + ALO + aA[0][ks]);
            ldsm4(al[1], cur + ALO + aA[1][ks]);
            #pragma unroll
            for (int bq = 0; bq < 4; bq++) ldsm4t(bh[bq], cur + BHI + aB[ks][bq]);
            #pragma unroll
            for (int bq = 0; bq < 4; bq++) ldsm4t(bl[bq], cur + BLO + aB[ks][bq]);

            #pragma unroll
            for (int mt = 0; mt < 2; mt++)
                #pragma unroll
                for (int nt = 0; nt < 8; nt++) {
                    const int bq = nt >> 1, of = (nt & 1) * 2;
                    mma_bf16(acc[mt][nt], ah[mt], bh[bq][of], bh[bq][of + 1]);
                }
            #pragma unroll
            for (int mt = 0; mt < 2; mt++)
                #pragma unroll
                for (int nt = 0; nt < 8; nt++) {
                    const int bq = nt >> 1, of = (nt & 1) * 2;
                    mma_bf16(acc[mt][nt], al[mt], bh[bq][of], bh[bq][of + 1]);
                }
            #pragma unroll
            for (int mt = 0; mt < 2; mt++)
                #pragma unroll
                for (int nt = 0; nt < 8; nt++) {
                    const int bq = nt >> 1, of = (nt & 1) * 2;
                    mma_bf16(acc[mt][nt], ah[mt], bl[bq][of], bl[bq][of + 1]);
                }
        }

        // store prefetched tile into next stage
        if (tile < 63) {
            cvt_store(nxt + AHI + sa0, nxt + ALO + sa0, ra0a, ra0b);
            cvt_store(nxt + AHI + sa1, nxt + ALO + sa1, ra1a, ra1b);
            cvt_store(nxt + BHI + sb0, nxt + BLO + sb0, rb0a, rb0b);
            cvt_store(nxt + BHI + sb1, nxt + BLO + sb1, rb1a, rb1b);
            __syncthreads();
        }
    }

    // ---- epilogue ----
    const int g  = lane >> 2;
    const int tc = lane & 3;
    #pragma unroll
    for (int mt = 0; mt < 2; mt++) {
        const size_t row0 = m0 + wm * 32 + mt * 16 + g;
        #pragma unroll
        for (int nt = 0; nt < 8; nt++) {
            const size_t col = n0 + wn * 64 + nt * 8 + tc * 2;
            float b0 = 0.0f, b1 = 0.0f;
            if (bias != nullptr) { b0 = bias[col]; b1 = bias[col + 1]; }
            float2 v0 = make_float2(acc[mt][nt][0] + b0, acc[mt][nt][1] + b1);
            float2 v1 = make_float2(acc[mt][nt][2] + b0, acc[mt][nt][3] + b1);
            *(float2*)(C + row0 * DD + col)       = v0;
            *(float2*)(C + (row0 + 8) * DD + col) = v1;
        }
    }
}

// ============================================================================
// Scan: 64 blocks, one per (b, n). W_n column-per-thread in regs (128 regs),
// state ping-pong in shared, f32x2 matvec with 8 accumulators, fast tanh,
// prefetch depth 3. One barrier per step.
// ============================================================================
__global__ __launch_bounds__(128, 1)
void scan_kernel(const float* __restrict__ x, const float* __restrict__ s0,
                 const float* __restrict__ SW, float* __restrict__ y) {
    const int b = blockIdx.x >> 4;
    const int n = blockIdx.x & 15;
    const int k = threadIdx.x;

    // W column k of head n in (even,odd)-h packed pairs: out[k] = sum_h s[h]*W[h][k]
    const float* Wn = SW + (size_t)n * HH * HH;
    ull w2[64];
    #pragma unroll
    for (int j = 0; j < 64; j++)
        w2[j] = pack2(Wn[(2 * j) * HH + k], Wn[(2 * j + 1) * HH + k]);

    __shared__ __align__(16) float sbuf[2][HH];
    sbuf[0][k] = s0[((size_t)b * NH + n) * HH + k];
    __syncthreads();

    const float* xp = x + (size_t)b * SS * DD + n * HH + k;
    float*       yp = y + (size_t)b * SS * DD + n * HH + k;

    float xa = xp[0];
    float xb = xp[DD];
    float xc = xp[2 * (size_t)DD];

    for (int t = 0; t < SS; t++) {
        float xn = 0.0f;
        if (t + 3 < SS) xn = xp[(size_t)(t + 3) * DD];

        const ulonglong2* s4 = (const ulonglong2*)sbuf[t & 1];
        ull a0 = 0ull, a1 = 0ull, a2 = 0ull, a3 = 0ull;
        ull a4 = 0ull, a5 = 0ull, a6 = 0ull, a7 = 0ull;
        #pragma unroll
        for (int j = 0; j < 8; j++) {
            ulonglong2 p = s4[4 * j];
            ulonglong2 q = s4[4 * j + 1];
            ulonglong2 r = s4[4 * j + 2];
            ulonglong2 s = s4[4 * j + 3];
            a0 = ffma2(p.x, w2[8 * j + 0], a0);
            a1 = ffma2(p.y, w2[8 * j + 1], a1);
            a2 = ffma2(q.x, w2[8 * j + 2], a2);
            a3 = ffma2(q.y, w2[8 * j + 3], a3);
            a4 = ffma2(r.x, w2[8 * j + 4], a4);
            a5 = ffma2(r.y, w2[8 * j + 5], a5);
            a6 = ffma2(s.x, w2[8 * j + 6], a6);
            a7 = ffma2(s.y, w2[8 * j + 7], a7);
        }
        ull s01 = addf2(a0, a1), s23 = addf2(a2, a3);
        ull s45 = addf2(a4, a5), s67 = addf2(a6, a7);
        ull sall = addf2(addf2(s01, s23), addf2(s45, s67));
        float lo, hi;
        unpack2(sall, lo, hi);
        float dot = lo + hi;

        float v = fast_tanh(dot + xa);
        yp[(size_t)t * DD] = v;
        sbuf[(t + 1) & 1][k] = v;

        xa = xb; xb = xc; xc = xn;
        __syncthreads();
    }
}

// ============================================================================
// Launch: input-proj GEMM -> scan -> output-proj GEMM
// ============================================================================
extern "C" void kernel_launch(void* const* d_in, const int* in_sizes, int n_in,
                              void* d_out, int out_size) {
    const float* input  = (const float*)d_in[0];
    const float* state0 = (const float*)d_in[1];
    const float* w_in   = (const float*)d_in[2];
    const float* b_in   = (const float*)d_in[3];
    const float* sw     = (const float*)d_in[4];
    const float* w_out  = (const float*)d_in[5];
    float* out = (float*)d_out;

    float* xbuf = nullptr;
    float* ybuf = nullptr;
    cudaGetSymbolAddress((void**)&xbuf, g_x);
    cudaGetSymbolAddress((void**)&ybuf, g_y);

    const int smem_bytes = 2 * STG;  // 65536
    cudaFuncSetAttribute(gemm_mma_kernel, cudaFuncAttributeMaxDynamicSharedMemorySize, smem_bytes);

    dim3 grid(DD / 128, MTOT / 128);  // (16, 128)
    gemm_mma_kernel<<<grid, 256, smem_bytes>>>(input, w_in, b_in, xbuf);
    scan_kernel<<<BB * NH, HH>>>(xbuf, state0, sw, ybuf);
    gemm_mma_kernel<<<grid, 256, smem_bytes>>>(ybuf, w_out, nullptr, out);
}

// round 5
// speedup vs baseline: 2.5469x; 1.2487x over previous
#include <cuda_runtime.h>
#include <math.h>
#include <stdint.h>

// Problem constants
#define BB 4
#define SS 4096
#define DD 2048
#define NH 16
#define HH 128
#define MTOT (BB * SS)   // 16384

// Chunked pipeline
#define NCH 4
#define CH  (SS / NCH)   // 1024

typedef unsigned long long ull;

// ---- packed fp32x2 helpers ----
__device__ __forceinline__ ull ffma2(ull a, ull b, ull c) {
    ull d;
    asm("fma.rn.f32x2 %0, %1, %2, %3;" : "=l"(d) : "l"(a), "l"(b), "l"(c));
    return d;
}
__device__ __forceinline__ ull addf2(ull a, ull b) {
    ull d;
    asm("add.rn.f32x2 %0, %1, %2;" : "=l"(d) : "l"(a), "l"(b));
    return d;
}
__device__ __forceinline__ ull pack2(float lo, float hi) {
    ull r;
    asm("mov.b64 %0, {%1, %2};" : "=l"(r) : "f"(lo), "f"(hi));
    return r;
}
__device__ __forceinline__ void unpack2(ull v, float& lo, float& hi) {
    asm("mov.b64 {%0, %1}, %2;" : "=f"(lo), "=f"(hi) : "l"(v));
}
__device__ __forceinline__ uint32_t smem_u32(const void* p) {
    uint32_t a;
    asm("{ .reg .u64 t; cvta.to.shared.u64 t, %1; cvt.u32.u64 %0, t; }" : "=r"(a) : "l"(p));
    return a;
}

// fast tanh: (e^{2x}-1)/(e^{2x}+1) via MUFU ex2/rcp; rel err ~1e-7
__device__ __forceinline__ float fast_tanh(float x) {
    float t = fminf(x * 2.885390081777927f, 80.0f);
    float e;
    asm("ex2.approx.f32 %0, %1;" : "=f"(e) : "f"(t));
    float r;
    asm("rcp.approx.f32 %0, %1;" : "=f"(r) : "f"(e + 1.0f));
    return (e - 1.0f) * r;
}

// ---- mma.sync / ldmatrix (plain PTX, assembles at compute_103) ----
__device__ __forceinline__ void ldsm4(uint32_t* r, uint32_t addr) {
    asm volatile("ldmatrix.sync.aligned.m8n8.x4.shared.b16 {%0,%1,%2,%3}, [%4];"
                 : "=r"(r[0]), "=r"(r[1]), "=r"(r[2]), "=r"(r[3]) : "r"(addr));
}
__device__ __forceinline__ void ldsm4t(uint32_t* r, uint32_t addr) {
    asm volatile("ldmatrix.sync.aligned.m8n8.x4.trans.shared.b16 {%0,%1,%2,%3}, [%4];"
                 : "=r"(r[0]), "=r"(r[1]), "=r"(r[2]), "=r"(r[3]) : "r"(addr));
}
__device__ __forceinline__ void mma_bf16(float* c, const uint32_t* a, uint32_t b0, uint32_t b1) {
    asm volatile("mma.sync.aligned.m16n8k16.row.col.f32.bf16.bf16.f32 "
                 "{%0,%1,%2,%3}, {%4,%5,%6,%7}, {%8,%9}, {%0,%1,%2,%3};"
                 : "+f"(c[0]), "+f"(c[1]), "+f"(c[2]), "+f"(c[3])
                 : "r"(a[0]), "r"(a[1]), "r"(a[2]), "r"(a[3]), "r"(b0), "r"(b1));
}

// ---- scratch (device globals; no allocation allowed) ----
__device__ float g_x[33554432];   // (B,S,D) post-input-projection (+bias)
__device__ float g_y[33554432];   // (B,S,D) scan outputs
__device__ float g_state[BB * NH * HH];  // carried scan state between chunks

// ============================================================================
// bf16 3-product-split GEMM via mma.sync (chunked over S):
//   C rows [b*SS + s_base + tile*128) for b = blockIdx.z
// Tile 128x128, BK=32, 256 threads = 8 warps (4M x 2N).
// ============================================================================
#define STG 32768
#define AHI 0
#define ALO 8192
#define BHI 16384
#define BLO 24576

__device__ __forceinline__ uint32_t aoff(int r, int c) {
    return (uint32_t)(r * 64 + ((c ^ ((r >> 1) & 3)) * 16));
}
__device__ __forceinline__ uint32_t boff(int kr, int c) {
    return (uint32_t)(kr * 256 + ((c ^ (kr & 7)) * 16));
}

__device__ __forceinline__ void cvt_store(uint32_t dhi, uint32_t dlo, float4 v0, float4 v1) {
    float f[8] = {v0.x, v0.y, v0.z, v0.w, v1.x, v1.y, v1.z, v1.w};
    uint32_t h[4], l[4];
    #pragma unroll
    for (int p = 0; p < 4; p++) {
        uint32_t hp;
        asm("cvt.rn.bf16x2.f32 %0, %1, %2;" : "=r"(hp) : "f"(f[2 * p + 1]), "f"(f[2 * p]));
        float h0 = __uint_as_float(hp << 16);
        float h1 = __uint_as_float(hp & 0xFFFF0000u);
        float l0 = f[2 * p] - h0;
        float l1 = f[2 * p + 1] - h1;
        uint32_t lp;
        asm("cvt.rn.bf16x2.f32 %0, %1, %2;" : "=r"(lp) : "f"(l1), "f"(l0));
        h[p] = hp; l[p] = lp;
    }
    asm volatile("st.shared.v4.b32 [%0], {%1,%2,%3,%4};"
                 :: "r"(dhi), "r"(h[0]), "r"(h[1]), "r"(h[2]), "r"(h[3]));
    asm volatile("st.shared.v4.b32 [%0], {%1,%2,%3,%4};"
                 :: "r"(dlo), "r"(l[0]), "r"(l[1]), "r"(l[2]), "r"(l[3]));
}

__global__ __launch_bounds__(256, 1)
void gemm_mma_kernel(const float* __restrict__ A, const float* __restrict__ W,
                     const float* __restrict__ bias, float* __restrict__ C,
                     int s_base) {
    extern __shared__ __align__(128) char smem[];
    const uint32_t sbase = smem_u32(smem);

    const int t    = threadIdx.x;
    const int lane = t & 31;
    const int wid  = t >> 5;
    const int wm   = wid >> 1;
    const int wn   = wid & 1;
    const size_t m0 = (size_t)blockIdx.z * SS + (size_t)s_base + (size_t)blockIdx.y * 128;
    const size_t n0 = (size_t)blockIdx.x * 128;

    const float* gA0 = A + (m0 + (t >> 2)) * DD + (t & 3) * 8;
    const float* gA1 = gA0 + (size_t)64 * DD;
    const float* gB0 = W + (size_t)(t >> 4) * DD + n0 + (t & 15) * 8;
    const float* gB1 = gB0 + (size_t)16 * DD;

    const uint32_t sa0 = aoff(t >> 2, t & 3);
    const uint32_t sa1 = aoff((t >> 2) + 64, t & 3);
    const uint32_t sb0 = boff(t >> 4, t & 15);
    const uint32_t sb1 = boff((t >> 4) + 16, t & 15);

    const int arow = wm * 32 + (lane & 7) + ((lane >> 3) & 1) * 8;
    const int akh  = (lane >> 4) & 1;
    uint32_t aA[2][2];
    #pragma unroll
    for (int mt = 0; mt < 2; mt++)
        #pragma unroll
        for (int ks = 0; ks < 2; ks++)
            aA[mt][ks] = aoff(arow + mt * 16, ks * 2 + akh);
    const int bpair = lane >> 4;
    const int bkr0  = ((lane >> 3) & 1) * 8 + (lane & 7);
    uint32_t aB[2][4];
    #pragma unroll
    for (int ks = 0; ks < 2; ks++)
        #pragma unroll
        for (int bq = 0; bq < 4; bq++)
            aB[ks][bq] = boff(ks * 16 + bkr0, wn * 8 + bq * 2 + bpair);

    float acc[2][8][4];
    #pragma unroll
    for (int mt = 0; mt < 2; mt++)
        #pragma unroll
        for (int nt = 0; nt < 8; nt++)
            #pragma unroll
            for (int i = 0; i < 4; i++) acc[mt][nt][i] = 0.0f;

    float4 ra0a, ra0b, ra1a, ra1b, rb0a, rb0b, rb1a, rb1b;

    ra0a = *(const float4*)(gA0);     ra0b = *(const float4*)(gA0 + 4);
    ra1a = *(const float4*)(gA1);     ra1b = *(const float4*)(gA1 + 4);
    rb0a = *(const float4*)(gB0);     rb0b = *(const float4*)(gB0 + 4);
    rb1a = *(const float4*)(gB1);     rb1b = *(const float4*)(gB1 + 4);
    {
        uint32_t s = sbase;
        cvt_store(s + AHI + sa0, s + ALO + sa0, ra0a, ra0b);
        cvt_store(s + AHI + sa1, s + ALO + sa1, ra1a, ra1b);
        cvt_store(s + BHI + sb0, s + BLO + sb0, rb0a, rb0b);
        cvt_store(s + BHI + sb1, s + BLO + sb1, rb1a, rb1b);
    }
    __syncthreads();

    for (int tile = 0; tile < 64; tile++) {
        const uint32_t cur = sbase + (uint32_t)(tile & 1) * STG;
        const uint32_t nxt = sbase + (uint32_t)((tile + 1) & 1) * STG;

        if (tile < 63) {
            gA0 += 32; gA1 += 32;
            gB0 += (size_t)32 * DD; gB1 += (size_t)32 * DD;
            ra0a = *(const float4*)(gA0);     ra0b = *(const float4*)(gA0 + 4);
            ra1a = *(const float4*)(gA1);     ra1b = *(const float4*)(gA1 + 4);
            rb0a = *(const float4*)(gB0);     rb0b = *(const float4*)(gB0 + 4);
            rb1a = *(const float4*)(gB1);     rb1b = *(const float4*)(gB1 + 4);
        }

        #pragma unroll
        for (int ks = 0; ks < 2; ks++) {
            uint32_t ah[2][4], al[2][4], bh[4][4], bl[4][4];
            ldsm4(ah[0], cur + AHI + aA[0][ks]);
            ldsm4(ah[1], cur + AHI + aA[1][ks]);
            ldsm4(al[0], cur + ALO + aA[0][ks]);
            ldsm4(al[1], cur + ALO + aA[1][ks]);
            #pragma unroll
            for (int bq = 0; bq < 4; bq++) ldsm4t(bh[bq], cur + BHI + aB[ks][bq]);
            #pragma unroll
            for (int bq = 0; bq < 4; bq++) ldsm4t(bl[bq], cur + BLO + aB[ks][bq]);

            #pragma unroll
            for (int mt = 0; mt < 2; mt++)
                #pragma unroll
                for (int nt = 0; nt < 8; nt++) {
                    const int bq = nt >> 1, of = (nt & 1) * 2;
                    mma_bf16(acc[mt][nt], ah[mt], bh[bq][of], bh[bq][of + 1]);
                }
            #pragma unroll
            for (int mt = 0; mt < 2; mt++)
                #pragma unroll
                for (int nt = 0; nt < 8; nt++) {
                    const int bq = nt >> 1, of = (nt & 1) * 2;
                    mma_bf16(acc[mt][nt], al[mt], bh[bq][of], bh[bq][of + 1]);
                }
            #pragma unroll
            for (int mt = 0; mt < 2; mt++)
                #pragma unroll
                for (int nt = 0; nt < 8; nt++) {
                    const int bq = nt >> 1, of = (nt & 1) * 2;
                    mma_bf16(acc[mt][nt], ah[mt], bl[bq][of], bl[bq][of + 1]);
                }
        }

        if (tile < 63) {
            cvt_store(nxt + AHI + sa0, nxt + ALO + sa0, ra0a, ra0b);
            cvt_store(nxt + AHI + sa1, nxt + ALO + sa1, ra1a, ra1b);
            cvt_store(nxt + BHI + sb0, nxt + BLO + sb0, rb0a, rb0b);
            cvt_store(nxt + BHI + sb1, nxt + BLO + sb1, rb1a, rb1b);
            __syncthreads();
        }
    }

    const int g  = lane >> 2;
    const int tc = lane & 3;
    #pragma unroll
    for (int mt = 0; mt < 2; mt++) {
        const size_t row0 = m0 + wm * 32 + mt * 16 + g;
        #pragma unroll
        for (int nt = 0; nt < 8; nt++) {
            const size_t col = n0 + wn * 64 + nt * 8 + tc * 2;
            float b0 = 0.0f, b1 = 0.0f;
            if (bias != nullptr) { b0 = bias[col]; b1 = bias[col + 1]; }
            float2 v0 = make_float2(acc[mt][nt][0] + b0, acc[mt][nt][1] + b1);
            float2 v1 = make_float2(acc[mt][nt][2] + b0, acc[mt][nt][3] + b1);
            *(float2*)(C + row0 * DD + col)       = v0;
            *(float2*)(C + (row0 + 8) * DD + col) = v1;
        }
    }
}

// ============================================================================
// Scan chunk: steps [s_base, s_base+s_len). Reads initial state from sin,
// writes final state to sfin. 64 blocks, one per (b, n).
// ============================================================================
__global__ __launch_bounds__(128, 1)
void scan_kernel(const float* __restrict__ x, const float* __restrict__ sin,
                 const float* __restrict__ SW, float* __restrict__ y,
                 float* __restrict__ sfin, int s_base, int s_len) {
    const int b = blockIdx.x >> 4;
    const int n = blockIdx.x & 15;
    const int k = threadIdx.x;

    const float* Wn = SW + (size_t)n * HH * HH;
    ull w2[64];
    #pragma unroll
    for (int j = 0; j < 64; j++)
        w2[j] = pack2(Wn[(2 * j) * HH + k], Wn[(2 * j + 1) * HH + k]);

    __shared__ __align__(16) float sbuf[2][HH];
    sbuf[0][k] = sin[((size_t)b * NH + n) * HH + k];
    __syncthreads();

    const float* xp = x + ((size_t)b * SS + s_base) * DD + n * HH + k;
    float*       yp = y + ((size_t)b * SS + s_base) * DD + n * HH + k;

    float xa = xp[0];
    float xb = xp[DD];
    float xc = xp[2 * (size_t)DD];
    float v = 0.0f;

    for (int t = 0; t < s_len; t++) {
        float xn = 0.0f;
        if (t + 3 < s_len) xn = xp[(size_t)(t + 3) * DD];

        const ulonglong2* s4 = (const ulonglong2*)sbuf[t & 1];
        ull a0 = 0ull, a1 = 0ull, a2 = 0ull, a3 = 0ull;
        ull a4 = 0ull, a5 = 0ull, a6 = 0ull, a7 = 0ull;
        #pragma unroll
        for (int j = 0; j < 8; j++) {
            ulonglong2 p = s4[4 * j];
            ulonglong2 q = s4[4 * j + 1];
            ulonglong2 r = s4[4 * j + 2];
            ulonglong2 s = s4[4 * j + 3];
            a0 = ffma2(p.x, w2[8 * j + 0], a0);
            a1 = ffma2(p.y, w2[8 * j + 1], a1);
            a2 = ffma2(q.x, w2[8 * j + 2], a2);
            a3 = ffma2(q.y, w2[8 * j + 3], a3);
            a4 = ffma2(r.x, w2[8 * j + 4], a4);
            a5 = ffma2(r.y, w2[8 * j + 5], a5);
            a6 = ffma2(s.x, w2[8 * j + 6], a6);
            a7 = ffma2(s.y, w2[8 * j + 7], a7);
        }
        ull s01 = addf2(a0, a1), s23 = addf2(a2, a3);
        ull s45 = addf2(a4, a5), s67 = addf2(a6, a7);
        ull sall = addf2(addf2(s01, s23), addf2(s45, s67));
        float lo, hi;
        unpack2(sall, lo, hi);
        float dot = lo + hi;

        v = fast_tanh(dot + xa);
        yp[(size_t)t * DD] = v;
        sbuf[(t + 1) & 1][k] = v;

        xa = xb; xb = xc; xc = xn;
        __syncthreads();
    }

    sfin[((size_t)b * NH + n) * HH + k] = v;
}

// ============================================================================
// Launch: chunked, overlapped pipeline via stream fork/join.
//   default: gin0..gin3, gout0..gout3 (gout_c waits on scan_c)
//   st1:     scan0..scan3 (scan_c waits on gin_c; state carried in g_state)
// ============================================================================
extern "C" void kernel_launch(void* const* d_in, const int* in_sizes, int n_in,
                              void* d_out, int out_size) {
    const float* input  = (const float*)d_in[0];
    const float* state0 = (const float*)d_in[1];
    const float* w_in   = (const float*)d_in[2];
    const float* b_in   = (const float*)d_in[3];
    const float* sw     = (const float*)d_in[4];
    const float* w_out  = (const float*)d_in[5];
    float* out = (float*)d_out;

    float* xbuf = nullptr;
    float* ybuf = nullptr;
    float* stbuf = nullptr;
    cudaGetSymbolAddress((void**)&xbuf, g_x);
    cudaGetSymbolAddress((void**)&ybuf, g_y);
    cudaGetSymbolAddress((void**)&stbuf, g_state);

    // Lazily create side stream + events (host-side resources, no device mem)
    static cudaStream_t st1 = nullptr;
    static cudaEvent_t ev_gin[NCH], ev_scan[NCH];
    if (st1 == nullptr) {
        cudaStreamCreateWithFlags(&st1, cudaStreamNonBlocking);
        for (int c = 0; c < NCH; c++) {
            cudaEventCreateWithFlags(&ev_gin[c], cudaEventDisableTiming);
            cudaEventCreateWithFlags(&ev_scan[c], cudaEventDisableTiming);
        }
    }

    const int smem_bytes = 2 * STG;  // 65536
    cudaFuncSetAttribute(gemm_mma_kernel, cudaFuncAttributeMaxDynamicSharedMemorySize, smem_bytes);

    dim3 ggrid(DD / 128, CH / 128, BB);  // (16, 8, 4) per chunk

    // Input-projection chunks on default stream
    for (int c = 0; c < NCH; c++) {
        gemm_mma_kernel<<<ggrid, 256, smem_bytes>>>(input, w_in, b_in, xbuf, c * CH);
        cudaEventRecord(ev_gin[c], 0);
    }

    // Scan chunks on side stream (sequential by state dependency)
    for (int c = 0; c < NCH; c++) {
        cudaStreamWaitEvent(st1, ev_gin[c], 0);
        const float* s_init = (c == 0) ? state0 : stbuf;
        scan_kernel<<<BB * NH, HH, 0, st1>>>(xbuf, s_init, sw, ybuf, stbuf, c * CH, CH);
        cudaEventRecord(ev_scan[c], st1);
    }

    // Output-projection chunks on default stream (joins the fork)
    for (int c = 0; c < NCH; c++) {
        cudaStreamWaitEvent(0, ev_scan[c], 0);
        gemm_mma_kernel<<<ggrid, 256, smem_bytes>>>(ybuf, w_out, nullptr, out, c * CH);
    }
}

// round 7
// speedup vs baseline: 2.9730x; 1.1673x over previous
#include <cuda_runtime.h>
#include <math.h>
#include <stdint.h>

// Problem constants
#define BB 4
#define SS 4096
#define DD 2048
#define NH 16
#define HH 128
#define MTOT (BB * SS)   // 16384

// Chunked pipeline
#define NCH 8
#define CH  (SS / NCH)   // 512

typedef unsigned long long ull;

// ---- packed fp32x2 helpers ----
__device__ __forceinline__ ull ffma2(ull a, ull b, ull c) {
    ull d;
    asm("fma.rn.f32x2 %0, %1, %2, %3;" : "=l"(d) : "l"(a), "l"(b), "l"(c));
    return d;
}
__device__ __forceinline__ ull addf2(ull a, ull b) {
    ull d;
    asm("add.rn.f32x2 %0, %1, %2;" : "=l"(d) : "l"(a), "l"(b));
    return d;
}
__device__ __forceinline__ ull pack2(float lo, float hi) {
    ull r;
    asm("mov.b64 %0, {%1, %2};" : "=l"(r) : "f"(lo), "f"(hi));
    return r;
}
__device__ __forceinline__ void unpack2(ull v, float& lo, float& hi) {
    asm("mov.b64 {%0, %1}, %2;" : "=f"(lo), "=f"(hi) : "l"(v));
}
__device__ __forceinline__ uint32_t smem_u32(const void* p) {
    uint32_t a;
    asm("{ .reg .u64 t; cvta.to.shared.u64 t, %1; cvt.u32.u64 %0, t; }" : "=r"(a) : "l"(p));
    return a;
}

// fast tanh: (e^{2x}-1)/(e^{2x}+1) via MUFU ex2/rcp; rel err ~1e-7
__device__ __forceinline__ float fast_tanh(float x) {
    float t = fminf(x * 2.885390081777927f, 80.0f);
    float e;
    asm("ex2.approx.f32 %0, %1;" : "=f"(e) : "f"(t));
    float r;
    asm("rcp.approx.f32 %0, %1;" : "=f"(r) : "f"(e + 1.0f));
    return (e - 1.0f) * r;
}

// ---- mma.sync / ldmatrix (plain PTX, assembles at compute_103) ----
__device__ __forceinline__ void ldsm4(uint32_t* r, uint32_t addr) {
    asm volatile("ldmatrix.sync.aligned.m8n8.x4.shared.b16 {%0,%1,%2,%3}, [%4];"
                 : "=r"(r[0]), "=r"(r[1]), "=r"(r[2]), "=r"(r[3]) : "r"(addr));
}
__device__ __forceinline__ void ldsm4t(uint32_t* r, uint32_t addr) {
    asm volatile("ldmatrix.sync.aligned.m8n8.x4.trans.shared.b16 {%0,%1,%2,%3}, [%4];"
                 : "=r"(r[0]), "=r"(r[1]), "=r"(r[2]), "=r"(r[3]) : "r"(addr));
}
__device__ __forceinline__ void mma_bf16(float* c, const uint32_t* a, uint32_t b0, uint32_t b1) {
    asm volatile("mma.sync.aligned.m16n8k16.row.col.f32.bf16.bf16.f32 "
                 "{%0,%1,%2,%3}, {%4,%5,%6,%7}, {%8,%9}, {%0,%1,%2,%3};"
                 : "+f"(c[0]), "+f"(c[1]), "+f"(c[2]), "+f"(c[3])
                 : "r"(a[0]), "r"(a[1]), "r"(a[2]), "r"(a[3]), "r"(b0), "r"(b1));
}

// ---- scratch (device globals; no allocation allowed) ----
__device__ float g_x[33554432];   // (B,S,D) post-input-projection (+bias)
__device__ float g_y[33554432];   // (B,S,D) scan outputs
__device__ float g_state[BB * NH * HH];  // carried scan state between chunks

// ============================================================================
// bf16 3-product-split GEMM via mma.sync (chunked over S):
// Tile 128x128, BK=32, 256 threads = 8 warps (4M x 2N).
// Single-stage 32KB smem, no register prefetch; 2 CTAs/SM cover latency.
// ============================================================================
#define AHI 0
#define ALO 8192
#define BHI 16384
#define BLO 24576

__device__ __forceinline__ uint32_t aoff(int r, int c) {
    return (uint32_t)(r * 64 + ((c ^ ((r >> 1) & 3)) * 16));
}
__device__ __forceinline__ uint32_t boff(int kr, int c) {
    return (uint32_t)(kr * 256 + ((c ^ (kr & 7)) * 16));
}

__device__ __forceinline__ void cvt_store(uint32_t dhi, uint32_t dlo, float4 v0, float4 v1) {
    float f[8] = {v0.x, v0.y, v0.z, v0.w, v1.x, v1.y, v1.z, v1.w};
    uint32_t h[4], l[4];
    #pragma unroll
    for (int p = 0; p < 4; p++) {
        uint32_t hp;
        asm("cvt.rn.bf16x2.f32 %0, %1, %2;" : "=r"(hp) : "f"(f[2 * p + 1]), "f"(f[2 * p]));
        float h0 = __uint_as_float(hp << 16);
        float h1 = __uint_as_float(hp & 0xFFFF0000u);
        float l0 = f[2 * p] - h0;
        float l1 = f[2 * p + 1] - h1;
        uint32_t lp;
        asm("cvt.rn.bf16x2.f32 %0, %1, %2;" : "=r"(lp) : "f"(l1), "f"(l0));
        h[p] = hp; l[p] = lp;
    }
    asm volatile("st.shared.v4.b32 [%0], {%1,%2,%3,%4};"
                 :: "r"(dhi), "r"(h[0]), "r"(h[1]), "r"(h[2]), "r"(h[3]));
    asm volatile("st.shared.v4.b32 [%0], {%1,%2,%3,%4};"
                 :: "r"(dlo), "r"(l[0]), "r"(l[1]), "r"(l[2]), "r"(l[3]));
}

__global__ __launch_bounds__(256, 2)
void gemm_mma_kernel(const float* __restrict__ A, const float* __restrict__ W,
                     const float* __restrict__ bias, float* __restrict__ C,
                     int s_base) {
    __shared__ __align__(128) char smem[32768];
    const uint32_t sb = smem_u32(smem);

    const int t    = threadIdx.x;
    const int lane = t & 31;
    const int wid  = t >> 5;
    const int wm   = wid >> 1;
    const int wn   = wid & 1;
    const size_t m0 = (size_t)blockIdx.z * SS + (size_t)s_base + (size_t)blockIdx.y * 128;
    const size_t n0 = (size_t)blockIdx.x * 128;

    const float* gA0 = A + (m0 + (t >> 2)) * DD + (t & 3) * 8;
    const float* gA1 = gA0 + (size_t)64 * DD;
    const float* gB0 = W + (size_t)(t >> 4) * DD + n0 + (t & 15) * 8;
    const float* gB1 = gB0 + (size_t)16 * DD;

    const uint32_t sa0 = sb + AHI + aoff(t >> 2, t & 3);
    const uint32_t sa1 = sb + AHI + aoff((t >> 2) + 64, t & 3);
    const uint32_t sb0 = sb + BHI + boff(t >> 4, t & 15);
    const uint32_t sb1 = sb + BHI + boff((t >> 4) + 16, t & 15);

    const int arow = wm * 32 + (lane & 7) + ((lane >> 3) & 1) * 8;
    const int akh  = (lane >> 4) & 1;
    uint32_t aA[2][2];
    #pragma unroll
    for (int mt = 0; mt < 2; mt++)
        #pragma unroll
        for (int ks = 0; ks < 2; ks++)
            aA[mt][ks] = sb + AHI + aoff(arow + mt * 16, ks * 2 + akh);
    const int bpair = lane >> 4;
    const int bkr0  = ((lane >> 3) & 1) * 8 + (lane & 7);
    uint32_t aB[2][4];
    #pragma unroll
    for (int ks = 0; ks < 2; ks++)
        #pragma unroll
        for (int bq = 0; bq < 4; bq++)
            aB[ks][bq] = sb + BHI + boff(ks * 16 + bkr0, wn * 8 + bq * 2 + bpair);

    float acc[2][8][4];
    #pragma unroll
    for (int mt = 0; mt < 2; mt++)
        #pragma unroll
        for (int nt = 0; nt < 8; nt++)
            #pragma unroll
            for (int i = 0; i < 4; i++) acc[mt][nt][i] = 0.0f;

    for (int tile = 0; tile < 64; tile++) {
        // Issue gmem loads first (latency overlaps prior compute tail + barrier)
        float4 ra0a = *(const float4*)(gA0);     float4 ra0b = *(const float4*)(gA0 + 4);
        float4 ra1a = *(const float4*)(gA1);     float4 ra1b = *(const float4*)(gA1 + 4);
        float4 rb0a = *(const float4*)(gB0);     float4 rb0b = *(const float4*)(gB0 + 4);
        float4 rb1a = *(const float4*)(gB1);     float4 rb1b = *(const float4*)(gB1 + 4);
        gA0 += 32; gA1 += 32;
        gB0 += (size_t)32 * DD; gB1 += (size_t)32 * DD;

        if (tile > 0) __syncthreads();   // previous compute done before overwrite
        cvt_store(sa0, sa0 + (ALO - AHI), ra0a, ra0b);
        cvt_store(sa1, sa1 + (ALO - AHI), ra1a, ra1b);
        cvt_store(sb0, sb0 + (BLO - BHI), rb0a, rb0b);
        cvt_store(sb1, sb1 + (BLO - BHI), rb1a, rb1b);
        __syncthreads();

        #pragma unroll
        for (int ks = 0; ks < 2; ks++) {
            uint32_t ah[2][4], al[2][4], bx[4][4];
            ldsm4(ah[0], aA[0][ks]);
            ldsm4(ah[1], aA[1][ks]);
            ldsm4(al[0], aA[0][ks] + (ALO - AHI));
            ldsm4(al[1], aA[1][ks] + (ALO - AHI));
            #pragma unroll
            for (int bq = 0; bq < 4; bq++) ldsm4t(bx[bq], aB[ks][bq]);

            #pragma unroll
            for (int mt = 0; mt < 2; mt++)
                #pragma unroll
                for (int nt = 0; nt < 8; nt++) {
                    const int bq = nt >> 1, of = (nt & 1) * 2;
                    mma_bf16(acc[mt][nt], ah[mt], bx[bq][of], bx[bq][of + 1]);
                }
            #pragma unroll
            for (int mt = 0; mt < 2; mt++)
                #pragma unroll
                for (int nt = 0; nt < 8; nt++) {
                    const int bq = nt >> 1, of = (nt & 1) * 2;
                    mma_bf16(acc[mt][nt], al[mt], bx[bq][of], bx[bq][of + 1]);
                }
            // reload bx <- B_lo (reuses registers)
            #pragma unroll
            for (int bq = 0; bq < 4; bq++) ldsm4t(bx[bq], aB[ks][bq] + (BLO - BHI));
            #pragma unroll
            for (int mt = 0; mt < 2; mt++)
                #pragma unroll
                for (int nt = 0; nt < 8; nt++) {
                    const int bq = nt >> 1, of = (nt & 1) * 2;
                    mma_bf16(acc[mt][nt], ah[mt], bx[bq][of], bx[bq][of + 1]);
                }
        }
    }

    const int g  = lane >> 2;
    const int tc = lane & 3;
    #pragma unroll
    for (int mt = 0; mt < 2; mt++) {
        const size_t row0 = m0 + wm * 32 + mt * 16 + g;
        #pragma unroll
        for (int nt = 0; nt < 8; nt++) {
            const size_t col = n0 + wn * 64 + nt * 8 + tc * 2;
            float b0 = 0.0f, b1 = 0.0f;
            if (bias != nullptr) { b0 = bias[col]; b1 = bias[col + 1]; }
            float2 v0 = make_float2(acc[mt][nt][0] + b0, acc[mt][nt][1] + b1);
            float2 v1 = make_float2(acc[mt][nt][2] + b0, acc[mt][nt][3] + b1);
            *(float2*)(C + row0 * DD + col)       = v0;
            *(float2*)(C + (row0 + 8) * DD + col) = v1;
        }
    }
}

// ============================================================================
// Scan chunk: steps [s_base, s_base+s_len). 64 blocks, one per (b, n).
// ============================================================================
__global__ __launch_bounds__(128, 1)
void scan_kernel(const float* __restrict__ x, const float* __restrict__ sin,
                 const float* __restrict__ SW, float* __restrict__ y,
                 float* __restrict__ sfin, int s_base, int s_len) {
    const int b = blockIdx.x >> 4;
    const int n = blockIdx.x & 15;
    const int k = threadIdx.x;

    const float* Wn = SW + (size_t)n * HH * HH;
    ull w2[64];
    #pragma unroll
    for (int j = 0; j < 64; j++)
        w2[j] = pack2(Wn[(2 * j) * HH + k], Wn[(2 * j + 1) * HH + k]);

    __shared__ __align__(16) float sbuf[2][HH];
    sbuf[0][k] = sin[((size_t)b * NH + n) * HH + k];
    __syncthreads();

    const float* xp = x + ((size_t)b * SS + s_base) * DD + n * HH + k;
    float*       yp = y + ((size_t)b * SS + s_base) * DD + n * HH + k;

    float xa = xp[0];
    float xb = xp[DD];
    float xc = xp[2 * (size_t)DD];
    float v = 0.0f;

    for (int t = 0; t < s_len; t++) {
        float xn = 0.0f;
        if (t + 3 < s_len) xn = xp[(size_t)(t + 3) * DD];

        const ulonglong2* s4 = (const ulonglong2*)sbuf[t & 1];
        ull a0 = 0ull, a1 = 0ull, a2 = 0ull, a3 = 0ull;
        ull a4 = 0ull, a5 = 0ull, a6 = 0ull, a7 = 0ull;
        #pragma unroll
        for (int j = 0; j < 8; j++) {
            ulonglong2 p = s4[4 * j];
            ulonglong2 q = s4[4 * j + 1];
            ulonglong2 r = s4[4 * j + 2];
            ulonglong2 s = s4[4 * j + 3];
            a0 = ffma2(p.x, w2[8 * j + 0], a0);
            a1 = ffma2(p.y, w2[8 * j + 1], a1);
            a2 = ffma2(q.x, w2[8 * j + 2], a2);
            a3 = ffma2(q.y, w2[8 * j + 3], a3);
            a4 = ffma2(r.x, w2[8 * j + 4], a4);
            a5 = ffma2(r.y, w2[8 * j + 5], a5);
            a6 = ffma2(s.x, w2[8 * j + 6], a6);
            a7 = ffma2(s.y, w2[8 * j + 7], a7);
        }
        ull s01 = addf2(a0, a1), s23 = addf2(a2, a3);
        ull s45 = addf2(a4, a5), s67 = addf2(a6, a7);
        ull sall = addf2(addf2(s01, s23), addf2(s45, s67));
        float lo, hi;
        unpack2(sall, lo, hi);
        float dot = lo + hi;

        v = fast_tanh(dot + xa);
        yp[(size_t)t * DD] = v;
        sbuf[(t + 1) & 1][k] = v;

        xa = xb; xb = xc; xc = xn;
        __syncthreads();
    }

    sfin[((size_t)b * NH + n) * HH + k] = v;
}

// ============================================================================
// Launch: 3-stream chunked pipeline.
//   origin stream: gin0..gin7
//   st1 (high prio): scan0..scan7 (scan_c waits gin_c)
//   st2: gout0..gout7 (gout_c waits scan_c); tail event joins origin.
// ============================================================================
extern "C" void kernel_launch(void* const* d_in, const int* in_sizes, int n_in,
                              void* d_out, int out_size) {
    const float* input  = (const float*)d_in[0];
    const float* state0 = (const float*)d_in[1];
    const float* w_in   = (const float*)d_in[2];
    const float* b_in   = (const float*)d_in[3];
    const float* sw     = (const float*)d_in[4];
    const float* w_out  = (const float*)d_in[5];
    float* out = (float*)d_out;

    float* xbuf = nullptr;
    float* ybuf = nullptr;
    float* stbuf = nullptr;
    cudaGetSymbolAddress((void**)&xbuf, g_x);
    cudaGetSymbolAddress((void**)&ybuf, g_y);
    cudaGetSymbolAddress((void**)&stbuf, g_state);

    static cudaStream_t st1 = nullptr, st2 = nullptr;
    static cudaEvent_t ev_gin[NCH], ev_scan[NCH], ev_tail;
    if (st1 == nullptr) {
        int prio_lo, prio_hi;
        cudaDeviceGetStreamPriorityRange(&prio_lo, &prio_hi);
        cudaStreamCreateWithPriority(&st1, cudaStreamNonBlocking, prio_hi);  // scan: highest
        cudaStreamCreateWithFlags(&st2, cudaStreamNonBlocking);
        for (int c = 0; c < NCH; c++) {
            cudaEventCreateWithFlags(&ev_gin[c], cudaEventDisableTiming);
            cudaEventCreateWithFlags(&ev_scan[c], cudaEventDisableTiming);
        }
        cudaEventCreateWithFlags(&ev_tail, cudaEventDisableTiming);
    }

    dim3 ggrid(DD / 128, CH / 128, BB);  // (16, 4, 4) per chunk

    // Input-projection chunks on origin stream
    for (int c = 0; c < NCH; c++) {
        gemm_mma_kernel<<<ggrid, 256>>>(input, w_in, b_in, xbuf, c * CH);
        cudaEventRecord(ev_gin[c], 0);
    }

    // Scan chunks on high-priority stream (sequential by state dependency)
    for (int c = 0; c < NCH; c++) {
        cudaStreamWaitEvent(st1, ev_gin[c], 0);
        const float* s_init = (c == 0) ? state0 : stbuf;
        scan_kernel<<<BB * NH, HH, 0, st1>>>(xbuf, s_init, sw, ybuf, stbuf, c * CH, CH);
        cudaEventRecord(ev_scan[c], st1);
    }

    // Output-projection chunks on st2 (overlap remaining gins)
    for (int c = 0; c < NCH; c++) {
        cudaStreamWaitEvent(st2, ev_scan[c], 0);
        gemm_mma_kernel<<<ggrid, 256, 0, st2>>>(ybuf, w_out, nullptr, out, c * CH);
    }

    // Join forked work back to origin stream for graph capture
    cudaEventRecord(ev_tail, st2);
    cudaStreamWaitEvent(0, ev_tail, 0);
}